// round 2
// baseline (speedup 1.0000x reference)
#include <cuda_runtime.h>
#include <cstddef>

// ---------------------------------------------------------------------------
// Problem constants
// ---------------------------------------------------------------------------
#define S_     4
#define E_     8
#define NATOMS 50000
#define MSP    12500          // atoms per species
#define ALPHA_ 0.1f

// ---------------------------------------------------------------------------
// Scratch (device globals; no allocations allowed)
//   g_bufA: H1 (E*N*256) and later H3 (E*N*160, aliased)
//   g_bufB: H2 (E*N*192)
// ---------------------------------------------------------------------------
__device__ float g_bufA[(size_t)E_ * NATOMS * 256];   // 409.6 MB
__device__ float g_bufB[(size_t)E_ * NATOMS * 192];   // 307.2 MB
__device__ float g_partials[6250];
__device__ int   g_idx_sel;   // 0 -> cand0 is idx, 1 -> cand1 is idx

// ---------------------------------------------------------------------------
// CELU (matches jax.nn.celu: x>0 ? x : alpha*expm1(x/alpha))
// ---------------------------------------------------------------------------
__device__ __forceinline__ float celu_f(float v) {
    return v > 0.0f ? v : ALPHA_ * expm1f(v * (1.0f / ALPHA_));
}

// ---------------------------------------------------------------------------
// Detect which 50000-int array is idx (values up to N-1) vs species (< S)
// ---------------------------------------------------------------------------
__global__ void detect_idx_kernel(const int* __restrict__ cand0) {
    __shared__ int sm[256];
    int m = 0;
    for (int i = threadIdx.x; i < NATOMS; i += 256) m = max(m, cand0[i]);
    sm[threadIdx.x] = m;
    __syncthreads();
    for (int st = 128; st > 0; st >>= 1) {
        if (threadIdx.x < st) sm[threadIdx.x] = max(sm[threadIdx.x], sm[threadIdx.x + st]);
        __syncthreads();
    }
    if (threadIdx.x == 0) g_idx_sel = (sm[0] >= S_) ? 0 : 1;
}

// ---------------------------------------------------------------------------
// Tiled batched GEMM + bias + CELU.
//   Per batch (s,e): Out[m,n] = act( sum_k A[m,k] * W[s,e,k,n] + bias[s,e,n] )
//   A rows: GATHER ? aev[idx[s*MSP+m]] : Hprev[e][s*MSP+m]
//   Out layout: [e][s*MSP+m][ND]
//   ASRC: 0=param(aev), 1=g_bufA, 2=g_bufB ; ODST: 1=g_bufA, 2=g_bufB
// Grid: x = E * ntiles (ntile fastest -> A-row reuse across e/ntiles in L2),
//       y = mtiles, z = S
// ---------------------------------------------------------------------------
template<int BM, int BN, int BK, int TM, int TN, int KD, int ND,
         bool GATHER, bool ACT, int ASRC, int ODST>
__global__ __launch_bounds__(256)
void gemm_kernel(const float* __restrict__ Aparam,
                 const float* __restrict__ W,
                 const float* __restrict__ Bias,
                 const int* __restrict__ idx_c0,
                 const int* __restrict__ idx_c1)
{
    static_assert((BM / TM) * (BN / TN) == 256, "256 threads");
    __shared__ float As[BK][BM];
    __shared__ float Bs[BK][BN];

    constexpr int NT = (ND + BN - 1) / BN;     // n tiles
    const int e  = blockIdx.x / NT;
    const int n0 = (blockIdx.x % NT) * BN;
    const int s  = blockIdx.z;
    const int m0 = blockIdx.y * BM;
    const int tid = threadIdx.x;

    const float* Abase = (ASRC == 0) ? Aparam : (ASRC == 1 ? g_bufA : g_bufB);
    float*       Out   = (ODST == 1) ? g_bufA : g_bufB;

    const float* Wse = W + (size_t)(s * E_ + e) * KD * ND;

    float acc[TM][TN];
#pragma unroll
    for (int i = 0; i < TM; i++)
#pragma unroll
        for (int j = 0; j < TN; j++) acc[i][j] = 0.0f;

    // A-tile loads: BM*BK/4 float4 (=256 for BM=128,BK=8) -> one per thread
    const int a_row = tid / (BK / 4);
    const int a_k4  = tid % (BK / 4);
    // B-tile loads: BK*BN/4 float4
    constexpr int B_LOADS = BK * BN / 4;
    const int b_row = tid / (BN / 4);
    const int b_c4  = tid % (BN / 4);

    const int tx = tid % (BN / TN);
    const int ty = tid / (BN / TN);

    const int gm_a = m0 + a_row;
    const float* arow_ptr = nullptr;
    if (gm_a < MSP) {
        if (GATHER) {
            const int* idx = g_idx_sel ? idx_c1 : idx_c0;
            arow_ptr = Abase + (size_t)idx[s * MSP + gm_a] * KD;
        } else {
            arow_ptr = Abase + ((size_t)e * NATOMS + (size_t)s * MSP + gm_a) * KD;
        }
    }

#pragma unroll 1
    for (int kk = 0; kk < KD; kk += BK) {
        // ---- load A tile (transposed into As[k][m]) ----
        float4 av = make_float4(0.f, 0.f, 0.f, 0.f);
        if (arow_ptr) av = *reinterpret_cast<const float4*>(arow_ptr + kk + a_k4 * 4);
        As[a_k4 * 4 + 0][a_row] = av.x;
        As[a_k4 * 4 + 1][a_row] = av.y;
        As[a_k4 * 4 + 2][a_row] = av.z;
        As[a_k4 * 4 + 3][a_row] = av.w;
        // ---- load B tile ----
        if (B_LOADS == 256 || tid < B_LOADS) {
            int col = n0 + b_c4 * 4;
            float4 bv = make_float4(0.f, 0.f, 0.f, 0.f);
            if (col < ND)
                bv = *reinterpret_cast<const float4*>(Wse + (size_t)(kk + b_row) * ND + col);
            *reinterpret_cast<float4*>(&Bs[b_row][b_c4 * 4]) = bv;
        }
        __syncthreads();

#pragma unroll
        for (int k = 0; k < BK; k++) {
            float af[TM], bf[TN];
#pragma unroll
            for (int i = 0; i < TM; i += 4)
                *reinterpret_cast<float4*>(&af[i]) =
                    *reinterpret_cast<const float4*>(&As[k][ty * TM + i]);
#pragma unroll
            for (int j = 0; j < TN; j += 4)
                *reinterpret_cast<float4*>(&bf[j]) =
                    *reinterpret_cast<const float4*>(&Bs[k][tx * TN + j]);
#pragma unroll
            for (int i = 0; i < TM; i++)
#pragma unroll
                for (int j = 0; j < TN; j++)
                    acc[i][j] = fmaf(af[i], bf[j], acc[i][j]);
        }
        __syncthreads();
    }

    // ---- epilogue: bias + CELU + store ----
    const float* bias = Bias + (size_t)(s * E_ + e) * ND;
#pragma unroll
    for (int i = 0; i < TM; i++) {
        int m = m0 + ty * TM + i;
        if (m >= MSP) continue;
        float* orow = Out + ((size_t)e * NATOMS + (size_t)s * MSP + m) * ND;
#pragma unroll
        for (int j = 0; j < TN; j += 4) {
            int n = n0 + tx * TN + j;
            if (n < ND) {
                float4 v;
                v.x = acc[i][j + 0] + bias[n + 0];
                v.y = acc[i][j + 1] + bias[n + 1];
                v.z = acc[i][j + 2] + bias[n + 2];
                v.w = acc[i][j + 3] + bias[n + 3];
                if (ACT) {
                    v.x = celu_f(v.x); v.y = celu_f(v.y);
                    v.z = celu_f(v.z); v.w = celu_f(v.w);
                }
                *reinterpret_cast<float4*>(orow + n) = v;
            }
        }
    }
}

// ---------------------------------------------------------------------------
// Layer 4: per atom, for each e: dot(h3[e,slot,0:160], W4[s,e]) ; add b4,
// mean over e. One warp per atom; 8 atoms per block; per-block partial sums.
// H3 lives in g_bufA ([e][slot][160]).
// ---------------------------------------------------------------------------
__global__ __launch_bounds__(256)
void layer4_kernel(const float* __restrict__ W4, const float* __restrict__ b4)
{
    const int warp = threadIdx.x >> 5;
    const int lane = threadIdx.x & 31;
    const int slot = blockIdx.x * 8 + warp;
    const int s = slot / MSP;

    float acc = 0.0f;
#pragma unroll
    for (int e = 0; e < E_; e++) {
        const float* h = g_bufA + ((size_t)e * NATOMS + slot) * 160;
        const float* w = W4 + (size_t)(s * E_ + e) * 160;
#pragma unroll
        for (int d = lane; d < 160; d += 32)
            acc = fmaf(h[d], w[d], acc);
    }
#pragma unroll
    for (int o = 16; o > 0; o >>= 1)
        acc += __shfl_down_sync(0xffffffffu, acc, o);

    __shared__ float ssum[8];
    if (lane == 0) {
        float bsum = 0.0f;
#pragma unroll
        for (int e = 0; e < E_; e++) bsum += b4[s * E_ + e];
        ssum[warp] = (acc + bsum) * (1.0f / E_);
    }
    __syncthreads();
    if (threadIdx.x == 0) {
        float t = 0.0f;
#pragma unroll
        for (int w = 0; w < 8; w++) t += ssum[w];
        g_partials[blockIdx.x] = t;
    }
}

// ---------------------------------------------------------------------------
// Final deterministic reduction of block partials -> out[0]
// ---------------------------------------------------------------------------
__global__ void reduce_kernel(float* __restrict__ out, int n)
{
    __shared__ float sm[256];
    float a = 0.0f;
    for (int i = threadIdx.x; i < n; i += 256) a += g_partials[i];
    sm[threadIdx.x] = a;
    __syncthreads();
    for (int st = 128; st > 0; st >>= 1) {
        if (threadIdx.x < st) sm[threadIdx.x] += sm[threadIdx.x + st];
        __syncthreads();
    }
    if (threadIdx.x == 0) out[0] = sm[0];
}

// ---------------------------------------------------------------------------
// Launch
// ---------------------------------------------------------------------------
extern "C" void kernel_launch(void* const* d_in, const int* in_sizes, int n_in,
                              void* d_out, int out_size)
{
    const float *aev = nullptr, *W1 = nullptr, *b1 = nullptr, *W2 = nullptr,
                *b2 = nullptr, *W3 = nullptr, *b3 = nullptr, *W4 = nullptr,
                *b4 = nullptr;
    const int *cand0 = nullptr, *cand1 = nullptr;

    for (int i = 0; i < n_in; i++) {
        switch (in_sizes[i]) {
            case 50400000: aev = (const float*)d_in[i]; break;   // [1,N,1008]
            case  8257536: W1  = (const float*)d_in[i]; break;   // [S,E,1008,256]
            case     8192: b1  = (const float*)d_in[i]; break;
            case  1572864: W2  = (const float*)d_in[i]; break;   // [S,E,256,192]
            case     6144: b2  = (const float*)d_in[i]; break;
            case   983040: W3  = (const float*)d_in[i]; break;   // [S,E,192,160]
            case     5120:                                        // b3 then W4
                if (!b3) b3 = (const float*)d_in[i];
                else     W4 = (const float*)d_in[i];
                break;
            case       32: b4  = (const float*)d_in[i]; break;
            case    50000:                                        // species / idx
                if (!cand0) cand0 = (const int*)d_in[i];
                else        cand1 = (const int*)d_in[i];
                break;
            default: break;
        }
    }

    const int mtiles = (MSP + 127) / 128;   // 98

    // 0) figure out which candidate int array is idx
    detect_idx_kernel<<<1, 256>>>(cand0 ? cand0 : cand1);

    // 1) layer 1: gather + [12500 x 1008 x 256] x 32 batches -> g_bufA (H1)
    {
        dim3 grid(E_ * 2 /*256/128*/, mtiles, S_);
        gemm_kernel<128, 128, 8, 8, 8, 1008, 256, true, true, 0, 1>
            <<<grid, 256>>>(aev, W1, b1, cand0, cand1);
    }
    // 2) layer 2: [12500 x 256 x 192] -> g_bufB (H2)
    {
        dim3 grid(E_ * 3 /*ceil(192/64)*/, mtiles, S_);
        gemm_kernel<128, 64, 8, 8, 4, 256, 192, false, true, 1, 2>
            <<<grid, 256>>>(nullptr, W2, b2, nullptr, nullptr);
    }
    // 3) layer 3: [12500 x 192 x 160] -> g_bufA (H3, aliases H1)
    {
        dim3 grid(E_ * 3 /*ceil(160/64)*/, mtiles, S_);
        gemm_kernel<128, 64, 8, 8, 4, 192, 160, false, true, 2, 1>
            <<<grid, 256>>>(nullptr, W3, b3, nullptr, nullptr);
    }
    // 4) layer 4 + ensemble mean + per-block partials
    layer4_kernel<<<NATOMS / 8, 256>>>(W4, b4);
    // 5) final reduction
    reduce_kernel<<<1, 256>>>((float*)d_out, NATOMS / 8);
}

// round 5
// speedup vs baseline: 2.1046x; 2.1046x over previous
#include <cuda_runtime.h>
#include <cuda_bf16.h>
#include <cstdint>
#include <cstddef>

// ---------------------------------------------------------------------------
// Problem constants
// ---------------------------------------------------------------------------
#define S_     4
#define E_     8
#define NATOMS 50000
#define MSP    12500
#define ALPHA_ 0.1f

typedef __nv_bfloat16 bf16;

// ---------------------------------------------------------------------------
// Scratch (device globals; no allocations allowed). 16B-aligned for cp.async.
// ---------------------------------------------------------------------------
__device__ __align__(16) bf16 g_Xh[(size_t)NATOMS * 1024];         // gathered aev hi (K padded)
__device__ __align__(16) bf16 g_Xl[(size_t)NATOMS * 1024];         // gathered aev lo
__device__ __align__(16) bf16 g_H1h[(size_t)E_ * NATOMS * 256];
__device__ __align__(16) bf16 g_H1l[(size_t)E_ * NATOMS * 256];
__device__ __align__(16) bf16 g_H2h[(size_t)E_ * NATOMS * 192];
__device__ __align__(16) bf16 g_H2l[(size_t)E_ * NATOMS * 192];
__device__ __align__(16) float g_H3[(size_t)E_ * NATOMS * 192];    // stride 192, cols<160 valid
__device__ __align__(16) bf16 g_W1h[(size_t)32 * 256 * 1024];      // [se][N][Kpad]
__device__ __align__(16) bf16 g_W1l[(size_t)32 * 256 * 1024];
__device__ __align__(16) bf16 g_W2h[(size_t)32 * 192 * 256];
__device__ __align__(16) bf16 g_W2l[(size_t)32 * 192 * 256];
__device__ __align__(16) bf16 g_W3h[(size_t)32 * 192 * 192];       // N padded 160->192
__device__ __align__(16) bf16 g_W3l[(size_t)32 * 192 * 192];
__device__ float g_partials[6250];
__device__ int   g_idx_sel;

// ---------------------------------------------------------------------------
// Helpers
// ---------------------------------------------------------------------------
__device__ __forceinline__ float celu_f(float v) {
    return v > 0.0f ? v : ALPHA_ * expm1f(v * (1.0f / ALPHA_));
}

__device__ __forceinline__ uint32_t smem_u32(const void* p) {
    uint32_t a;
    asm("{ .reg .u64 t; cvta.to.shared.u64 t, %1; cvt.u32.u64 %0, t; }" : "=r"(a) : "l"(p));
    return a;
}

__device__ __forceinline__ void cp16(uint32_t dst, const void* src) {
    asm volatile("cp.async.cg.shared.global [%0], [%1], 16;" :: "r"(dst), "l"(src));
}
__device__ __forceinline__ void cp_commit() { asm volatile("cp.async.commit_group;" ::: "memory"); }
template<int N> __device__ __forceinline__ void cp_wait() {
    asm volatile("cp.async.wait_group %0;" :: "n"(N) : "memory");
}

__device__ __forceinline__ void ldsm4(uint32_t* r, uint32_t a) {
    asm volatile("ldmatrix.sync.aligned.m8n8.x4.shared.b16 {%0,%1,%2,%3}, [%4];"
                 : "=r"(r[0]), "=r"(r[1]), "=r"(r[2]), "=r"(r[3]) : "r"(a));
}

__device__ __forceinline__ void mma16816(float* d, const uint32_t* a, const uint32_t* b) {
    asm volatile(
        "mma.sync.aligned.m16n8k16.row.col.f32.bf16.bf16.f32 "
        "{%0,%1,%2,%3}, {%4,%5,%6,%7}, {%8,%9}, {%0,%1,%2,%3};"
        : "+f"(d[0]), "+f"(d[1]), "+f"(d[2]), "+f"(d[3])
        : "r"(a[0]), "r"(a[1]), "r"(a[2]), "r"(a[3]), "r"(b[0]), "r"(b[1]));
}

__device__ __forceinline__ void split_bf16(float v, bf16& h, bf16& l) {
    h = __float2bfloat16(v);
    l = __float2bfloat16(v - __bfloat162float(h));
}

// ---------------------------------------------------------------------------
// Detect which 50000-int array is idx (values up to N-1) vs species (< S)
// ---------------------------------------------------------------------------
__global__ void detect_idx_kernel(const int* __restrict__ cand0) {
    __shared__ int sm[256];
    int m = 0;
    for (int i = threadIdx.x; i < NATOMS; i += 256) m = max(m, cand0[i]);
    sm[threadIdx.x] = m;
    __syncthreads();
    for (int st = 128; st > 0; st >>= 1) {
        if (threadIdx.x < st) sm[threadIdx.x] = max(sm[threadIdx.x], sm[threadIdx.x + st]);
        __syncthreads();
    }
    if (threadIdx.x == 0) g_idx_sel = (sm[0] >= S_) ? 0 : 1;
}

// ---------------------------------------------------------------------------
// Gather aev rows per species order + bf16 hi/lo split, K zero-padded to 1024
// ---------------------------------------------------------------------------
__global__ __launch_bounds__(256)
void gather_split_kernel(const float* __restrict__ aev,
                         const int* __restrict__ c0, const int* __restrict__ c1)
{
    const int slot = blockIdx.x;                 // 0..49999 (= s*MSP + m)
    const int* idx = g_idx_sel ? c1 : c0;
    const float* src = aev + (size_t)idx[slot] * 1008;
    const size_t dst = (size_t)slot * 1024;
#pragma unroll
    for (int k = threadIdx.x; k < 1024; k += 256) {
        float v = (k < 1008) ? src[k] : 0.0f;
        bf16 h, l; split_bf16(v, h, l);
        g_Xh[dst + k] = h;
        g_Xl[dst + k] = l;
    }
}

// ---------------------------------------------------------------------------
// Weight transpose + bf16 hi/lo split: W[b][K][N] -> Wt[b][Npad][Kpad]
// ---------------------------------------------------------------------------
template<int LAYER, int K, int N, int KP, int NP>
__global__ void wsplit_kernel(const float* __restrict__ W)
{
    __shared__ float tile[32][33];
    const int b  = blockIdx.z;
    const int k0 = blockIdx.x * 32, n0 = blockIdx.y * 32;
    const float* Wb = W + (size_t)b * K * N;
    bf16 *Wh, *Wl;
    if constexpr (LAYER == 1)      { Wh = g_W1h; Wl = g_W1l; }
    else if constexpr (LAYER == 2) { Wh = g_W2h; Wl = g_W2l; }
    else                           { Wh = g_W3h; Wl = g_W3l; }

    for (int r = threadIdx.y; r < 32; r += 8) {
        int k = k0 + r, n = n0 + threadIdx.x;
        tile[r][threadIdx.x] = (k < K && n < N) ? Wb[(size_t)k * N + n] : 0.0f;
    }
    __syncthreads();
    for (int r = threadIdx.y; r < 32; r += 8) {
        int n = n0 + r, k = k0 + threadIdx.x;
        if (n < NP && k < KP) {
            float v = tile[threadIdx.x][r];
            bf16 h, l; split_bf16(v, h, l);
            size_t o = ((size_t)b * NP + n) * KP + k;
            Wh[o] = h; Wl[o] = l;
        }
    }
}

// ---------------------------------------------------------------------------
// mma.sync bf16 3-product GEMM + bias + CELU.
//   D[128 x CTAN] = A[128 x KPAD] * Wt[CTAN x KPAD]^T  per (s,e,mtile,ntile)
//   CTA: 8 warps as 4(m) x 2(n); warp tile 32 x WN; k-chunk 64, double buffer.
//   SMEM rows: 128B, swizzle u' = u ^ (row & 7) -> conflict-free ldmatrix.
// ---------------------------------------------------------------------------
template<int LAYER, int KPAD, int NDL, int NPAD, int OSTRIDE, int WN>
__global__ __launch_bounds__(256)
void mma_gemm_kernel(const float* __restrict__ Bias)
{
    constexpr int NCH    = KPAD / 64;
    constexpr int CTAN   = 2 * WN;
    constexpr int NF     = WN / 8;           // n8 frags per warp
    constexpr int BBYTES = CTAN * 128;       // one half (hi or lo)
    constexpr int STAGE  = 32768 + 2 * BBYTES;
    constexpr int AU     = 2048;             // 128 rows * 8 units * 2 halves
    constexpr int BU     = CTAN * 16;        // CTAN rows * 8 units * 2 halves

    extern __shared__ char smem[];
    const uint32_t sbase = smem_u32(smem);

    const int tid  = threadIdx.x;
    const int lane = tid & 31;
    const int wid  = tid >> 5;
    const int wm   = wid >> 1;               // 0..3
    const int wn   = wid & 1;                // 0..1
    const int m0   = blockIdx.x * 128;
    const int nt   = blockIdx.y;
    const int z    = blockIdx.z;             // s*E + e
    const int s    = z >> 3;
    const int e    = z & 7;

    const bf16 *Ah, *Al, *Wh, *Wl;
    if constexpr (LAYER == 1)      { Ah = g_Xh;  Al = g_Xl;  Wh = g_W1h; Wl = g_W1l; }
    else if constexpr (LAYER == 2) { Ah = g_H1h; Al = g_H1l; Wh = g_W2h; Wl = g_W2l; }
    else                           { Ah = g_H2h; Al = g_H2l; Wh = g_W3h; Wl = g_W3l; }

    auto load_chunk = [&](int ch, int st) {
        const uint32_t sb = sbase + st * STAGE;
#pragma unroll
        for (int i = tid; i < AU; i += 256) {
            const int half = i >> 10, rem = i & 1023, row = rem >> 3, u = rem & 7;
            int m = m0 + row; if (m >= MSP) m = MSP - 1;     // clamp; masked in epilogue
            size_t off;
            if constexpr (LAYER == 1) off = (size_t)(s * MSP + m) * KPAD;
            else                      off = ((size_t)e * NATOMS + (size_t)s * MSP + m) * KPAD;
            const bf16* src = (half ? Al : Ah) + off + ch * 64 + u * 8;
            cp16(sb + half * 16384 + row * 128 + ((u ^ (row & 7)) << 4), src);
        }
#pragma unroll
        for (int i = tid; i < BU; i += 256) {
            const int half = i / (BU / 2), rem = i % (BU / 2), row = rem >> 3, u = rem & 7;
            const int n = nt * CTAN + row;                   // < NPAD by construction
            const bf16* src = (half ? Wl : Wh) + ((size_t)z * NPAD + n) * KPAD + ch * 64 + u * 8;
            cp16(sb + 32768 + half * BBYTES + row * 128 + ((u ^ (row & 7)) << 4), src);
        }
    };

    float acc[2][NF][4];
#pragma unroll
    for (int a = 0; a < 2; a++)
#pragma unroll
        for (int b = 0; b < NF; b++)
#pragma unroll
            for (int c = 0; c < 4; c++) acc[a][b][c] = 0.0f;

    auto compute = [&](int st) {
        const uint32_t sb = sbase + st * STAGE;
        const int rl = lane & 15;
        const int usel = lane >> 4;
#pragma unroll
        for (int ks = 0; ks < 4; ks++) {
            uint32_t ah[2][4], al[2][4], bh[NF][2], bl[NF][2];
            const int uk = 2 * ks + usel;
#pragma unroll
            for (int mi = 0; mi < 2; mi++) {
                const int r = wm * 32 + mi * 16 + rl;
                const uint32_t ad = sb + r * 128 + ((uk ^ (r & 7)) << 4);
                ldsm4(ah[mi], ad);
                ldsm4(al[mi], ad + 16384);
            }
#pragma unroll
            for (int q = 0; q < NF / 2; q++) {
                const int r = wn * WN + q * 16 + rl;
                const uint32_t bd = sb + 32768 + r * 128 + ((uk ^ (r & 7)) << 4);
                uint32_t t[4];
                ldsm4(t, bd);
                bh[2 * q][0] = t[0]; bh[2 * q + 1][0] = t[1];
                bh[2 * q][1] = t[2]; bh[2 * q + 1][1] = t[3];
                ldsm4(t, bd + BBYTES);
                bl[2 * q][0] = t[0]; bl[2 * q + 1][0] = t[1];
                bl[2 * q][1] = t[2]; bl[2 * q + 1][1] = t[3];
            }
#pragma unroll
            for (int mi = 0; mi < 2; mi++)
#pragma unroll
                for (int j = 0; j < NF; j++) {
                    mma16816(acc[mi][j], ah[mi], bh[j]);   // hi*hi
                    mma16816(acc[mi][j], ah[mi], bl[j]);   // hi*lo
                    mma16816(acc[mi][j], al[mi], bh[j]);   // lo*hi
                }
        }
    };

    // ---- pipeline ----
    load_chunk(0, 0);
    cp_commit();
#pragma unroll 1
    for (int ch = 0; ch < NCH; ch++) {
        if (ch + 1 < NCH) {
            load_chunk(ch + 1, (ch + 1) & 1);
            cp_commit();
            cp_wait<1>();
        } else {
            cp_wait<0>();
        }
        __syncthreads();
        compute(ch & 1);
        __syncthreads();
    }

    // ---- epilogue: bias + CELU (+ bf16 split for next layer) ----
    const float* bias = Bias + (size_t)z * NDL;
#pragma unroll
    for (int mi = 0; mi < 2; mi++) {
#pragma unroll
        for (int j = 0; j < NF; j++) {
            const int n = nt * CTAN + wn * WN + j * 8 + 2 * (lane & 3);
            if (n >= NDL) continue;                       // L3 padded cols
            const float bv0 = bias[n], bv1 = bias[n + 1];
#pragma unroll
            for (int p = 0; p < 2; p++) {
                const int m = m0 + wm * 32 + mi * 16 + (lane >> 2) + p * 8;
                if (m >= MSP) continue;
                float v0 = celu_f(acc[mi][j][2 * p + 0] + bv0);
                float v1 = celu_f(acc[mi][j][2 * p + 1] + bv1);
                const size_t o = ((size_t)e * NATOMS + (size_t)s * MSP + m) * OSTRIDE + n;
                if constexpr (LAYER == 1) {
                    bf16 h0, l0, h1, l1;
                    split_bf16(v0, h0, l0); split_bf16(v1, h1, l1);
                    *reinterpret_cast<__nv_bfloat162*>(&g_H1h[o]) = __halves2bfloat162(h0, h1);
                    *reinterpret_cast<__nv_bfloat162*>(&g_H1l[o]) = __halves2bfloat162(l0, l1);
                } else if constexpr (LAYER == 2) {
                    bf16 h0, l0, h1, l1;
                    split_bf16(v0, h0, l0); split_bf16(v1, h1, l1);
                    *reinterpret_cast<__nv_bfloat162*>(&g_H2h[o]) = __halves2bfloat162(h0, h1);
                    *reinterpret_cast<__nv_bfloat162*>(&g_H2l[o]) = __halves2bfloat162(l0, l1);
                } else {
                    g_H3[o]     = v0;
                    g_H3[o + 1] = v1;
                }
            }
        }
    }
}

// ---------------------------------------------------------------------------
// Layer 4 + ensemble mean; warp per atom; per-block partials (deterministic)
// ---------------------------------------------------------------------------
__global__ __launch_bounds__(256)
void layer4_kernel(const float* __restrict__ W4, const float* __restrict__ b4)
{
    const int warp = threadIdx.x >> 5;
    const int lane = threadIdx.x & 31;
    const int slot = blockIdx.x * 8 + warp;
    const int s = slot / MSP;

    float acc = 0.0f;
#pragma unroll
    for (int e = 0; e < E_; e++) {
        const float* h = g_H3 + ((size_t)e * NATOMS + slot) * 192;
        const float* w = W4 + (size_t)(s * E_ + e) * 160;
#pragma unroll
        for (int d = lane; d < 160; d += 32)
            acc = fmaf(h[d], w[d], acc);
    }
#pragma unroll
    for (int o = 16; o > 0; o >>= 1)
        acc += __shfl_down_sync(0xffffffffu, acc, o);

    __shared__ float ssum[8];
    if (lane == 0) {
        float bsum = 0.0f;
#pragma unroll
        for (int e = 0; e < E_; e++) bsum += b4[s * E_ + e];
        ssum[warp] = (acc + bsum) * (1.0f / E_);
    }
    __syncthreads();
    if (threadIdx.x == 0) {
        float t = 0.0f;
#pragma unroll
        for (int w = 0; w < 8; w++) t += ssum[w];
        g_partials[blockIdx.x] = t;
    }
}

__global__ void reduce_kernel(float* __restrict__ out, int n)
{
    __shared__ float sm[256];
    float a = 0.0f;
    for (int i = threadIdx.x; i < n; i += 256) a += g_partials[i];
    sm[threadIdx.x] = a;
    __syncthreads();
    for (int st = 128; st > 0; st >>= 1) {
        if (threadIdx.x < st) sm[threadIdx.x] += sm[threadIdx.x + st];
        __syncthreads();
    }
    if (threadIdx.x == 0) out[0] = sm[0];
}

// ---------------------------------------------------------------------------
// Launch
// ---------------------------------------------------------------------------
extern "C" void kernel_launch(void* const* d_in, const int* in_sizes, int n_in,
                              void* d_out, int out_size)
{
    const float *aev = nullptr, *W1 = nullptr, *b1 = nullptr, *W2 = nullptr,
                *b2 = nullptr, *W3 = nullptr, *b3 = nullptr, *W4 = nullptr,
                *b4 = nullptr;
    const int *cand0 = nullptr, *cand1 = nullptr;

    for (int i = 0; i < n_in; i++) {
        switch (in_sizes[i]) {
            case 50400000: aev = (const float*)d_in[i]; break;
            case  8257536: W1  = (const float*)d_in[i]; break;
            case     8192: b1  = (const float*)d_in[i]; break;
            case  1572864: W2  = (const float*)d_in[i]; break;
            case     6144: b2  = (const float*)d_in[i]; break;
            case   983040: W3  = (const float*)d_in[i]; break;
            case     5120: if (!b3) b3 = (const float*)d_in[i];
                           else     W4 = (const float*)d_in[i]; break;
            case       32: b4  = (const float*)d_in[i]; break;
            case    50000: if (!cand0) cand0 = (const int*)d_in[i];
                           else        cand1 = (const int*)d_in[i]; break;
            default: break;
        }
    }

    // SMEM: L1 (WN=64): 2*(32768 + 2*128*128) = 131072; L2/L3 (WN=32): 98304
    cudaFuncSetAttribute(mma_gemm_kernel<1, 1024, 256, 256, 256, 64>,
                         cudaFuncAttributeMaxDynamicSharedMemorySize, 131072);
    cudaFuncSetAttribute(mma_gemm_kernel<2, 256, 192, 192, 192, 32>,
                         cudaFuncAttributeMaxDynamicSharedMemorySize, 98304);
    cudaFuncSetAttribute(mma_gemm_kernel<3, 192, 160, 192, 192, 32>,
                         cudaFuncAttributeMaxDynamicSharedMemorySize, 98304);

    // 0) idx vs species detection, then prep
    detect_idx_kernel<<<1, 256>>>(cand0 ? cand0 : cand1);
    gather_split_kernel<<<NATOMS, 256>>>(aev, cand0, cand1);
    wsplit_kernel<1, 1008, 256, 1024, 256><<<dim3(32, 8, 32), dim3(32, 8)>>>(W1);
    wsplit_kernel<2,  256, 192,  256, 192><<<dim3( 8, 6, 32), dim3(32, 8)>>>(W2);
    wsplit_kernel<3,  192, 160,  192, 192><<<dim3( 6, 6, 32), dim3(32, 8)>>>(W3);

    // 1) layer 1: [12500 x 1024 x 256] x 32 -> H1 (bf16 hi/lo)
    mma_gemm_kernel<1, 1024, 256, 256, 256, 64>
        <<<dim3(98, 2, 32), 256, 131072>>>(b1);
    // 2) layer 2: [12500 x 256 x 192] -> H2 (bf16 hi/lo)
    mma_gemm_kernel<2, 256, 192, 192, 192, 32>
        <<<dim3(98, 3, 32), 256, 98304>>>(b2);
    // 3) layer 3: [12500 x 192 x 160(pad 192)] -> H3 (fp32)
    mma_gemm_kernel<3, 192, 160, 192, 192, 32>
        <<<dim3(98, 3, 32), 256, 98304>>>(b3);
    // 4) layer 4 + ensemble mean
    layer4_kernel<<<NATOMS / 8, 256>>>(W4, b4);
    // 5) final deterministic reduction
    reduce_kernel<<<1, 256>>>((float*)d_out, NATOMS / 8);
}